// round 1
// baseline (speedup 1.0000x reference)
#include <cuda_runtime.h>
#include <math.h>

#define FEAT 7
#define PIX 49        // 7*7
#define PAD 81        // 9*9 zero-padded channel plane
#define STEPS 9

// ---------------- transposed weight scratch (device globals; no allocation) ----
// layout: Wt[(c*9 + k) * O + o]  (o fastest -> coalesced across threads)
__device__ float g_wt_conv0[2304 * 128];   // C=256, CK=2304, O=128
__device__ float g_wt_conv1[1152 * 128];   // C=128, CK=1152, O=128
__device__ float g_wt_cx0 [1179 * 256];    // C=131, CK=1179, O=256
__device__ float g_wt_ch0 [ 576 * 256];    // C=64,  CK=576,  O=256
__device__ float g_wt_cx1 [ 576 * 256];
__device__ float g_wt_ch1 [ 576 * 256];

__global__ void transpose_all(const float* __restrict__ w0, const float* __restrict__ w1,
                              const float* __restrict__ wcx0, const float* __restrict__ wch0,
                              const float* __restrict__ wcx1, const float* __restrict__ wch1)
{
    int i = blockIdx.x * blockDim.x + threadIdx.x;
    const int s0 = 128 * 2304, s1 = 128 * 1152, s2 = 256 * 1179, s3 = 256 * 576;
    if (i < s0) { int o = i / 2304, ck = i % 2304; g_wt_conv0[ck * 128 + o] = w0[i]; return; }
    i -= s0;
    if (i < s1) { int o = i / 1152, ck = i % 1152; g_wt_conv1[ck * 128 + o] = w1[i]; return; }
    i -= s1;
    if (i < s2) { int o = i / 1179, ck = i % 1179; g_wt_cx0[ck * 256 + o] = wcx0[i]; return; }
    i -= s2;
    if (i < s3) { int o = i / 576, ck = i % 576; g_wt_ch0[ck * 256 + o] = wch0[i]; return; }
    i -= s3;
    if (i < s3) { int o = i / 576, ck = i % 576; g_wt_cx1[ck * 256 + o] = wcx1[i]; return; }
    i -= s3;
    if (i < s3) { int o = i / 576, ck = i % 576; g_wt_ch1[ck * 256 + o] = wch1[i]; return; }
}

// 3x3 SAME conv accumulate. Thread owns output channel `o`, pixels [PS, PS+PC).
// Input is padded [C][81]; value at (y,x) lives at (y+1)*9+(x+1) = p + 2*(p/7) + 10.
// For output pixel p and tap k=(ky,kx), input address = p9 + ky*9 + kx, p9 = p + 2*(p/7).
// PC/PS/O are compile-time -> all SMEM accesses are [reg + imm], accs stay in regs.
template <int PC, int PS, int O>
__device__ __forceinline__ void conv_acc(const float* __restrict__ Wt, const int C,
                                         const float* __restrict__ in, const int o,
                                         float* acc)
{
    const float* wp = Wt + o;
    for (int c = 0; c < C; ++c) {
        const float* ib = in + c * PAD;
        const float* wc = wp + c * 9 * O;
#pragma unroll
        for (int k = 0; k < 9; ++k) {
            const float wv = __ldg(wc + k * O);
            const int k9 = (k / 3) * 9 + (k % 3);
#pragma unroll
            for (int pi = 0; pi < PC; ++pi) {
                const int p = PS + pi;
                acc[pi] = fmaf(wv, ib[p + 2 * (p / 7) + k9], acc[pi]);
            }
        }
    }
}

__device__ __forceinline__ float sigm(float v) { return 1.0f / (1.0f + expf(-v)); }

// ---------------- SMEM layout (floats) ----------------
// Phase B (recurrence):
//   inpP  @ 0      : 131*81 = 10611   (x feats ch0..127, v_p2=128, v_p1=129, v_first=130)
//   h0P   @ 10611  : 64*81  = 5184
//   h1P   @ 15795  : 64*81  = 5184
//   c0    @ 20979  : 3136
//   c1    @ 24115  : 3136
//   gates @ 27251  : 256*49 = 12544  (ends 39795)
//   logits@ 39795  : 50 ; pred int @ 39850
// Phase A overlays:
//   xin   @ 0      : 256*81 = 20736  (inside inpP+h0P+h1P region)
//   xoutP @ 20979  : 128*81 = 10368  (inside c0/c1/gates region)
#define SMEM_FLOATS 39872

__global__ __launch_bounds__(256, 1)
void polyrnn_main(const float* __restrict__ x, const int* __restrict__ first_vertex,
                  const float* __restrict__ b0, const float* __restrict__ b1,
                  const float* __restrict__ bcx0, const float* __restrict__ bch0,
                  const float* __restrict__ bcx1, const float* __restrict__ bch1,
                  const float* __restrict__ fcw, const float* __restrict__ fcb,
                  float* __restrict__ out)
{
    extern __shared__ float sm[];
    float* inpP  = sm;
    float* h0P   = sm + 10611;
    float* h1P   = sm + 15795;
    float* c0s   = sm + 20979;
    float* gsm   = sm + 27251;
    float* lg    = sm + 39795;
    int*   predp = (int*)(sm + 39850);
    float* xin   = sm;
    float* xoutP = sm + 20979;
    float* c1s   = sm + 24115;

    const int s   = blockIdx.x;
    const int tid = threadIdx.x;

    // ---- 1: zero xin + xoutP (padded planes need zero borders) ----
    for (int i = tid; i < 20736; i += 256) xin[i] = 0.0f;
    for (int i = tid; i < 10368; i += 256) xoutP[i] = 0.0f;
    __syncthreads();

    // ---- 2: load x into padded planes ----
    const float* xs = x + (size_t)s * (256 * PIX);
    for (int i = tid; i < 256 * PIX; i += 256) {
        int c = i / PIX, p = i % PIX;
        xin[c * PAD + p + 2 * (p / 7) + 10] = xs[i];
    }
    __syncthreads();

    // ---- 3: conv0 (256->128) + ReLU -> xoutP ----
    {
        const int o = tid & 127;
        const int half = tid >> 7;
        const float bias = b0[o];
        if (half == 0) {
            float a[25];
#pragma unroll
            for (int i = 0; i < 25; ++i) a[i] = bias;
            conv_acc<25, 0, 128>(g_wt_conv0, 256, xin, o, a);
#pragma unroll
            for (int i = 0; i < 25; ++i) {
                const int p = i;
                xoutP[o * PAD + p + 2 * (p / 7) + 10] = fmaxf(a[i], 0.0f);
            }
        } else {
            float a[24];
#pragma unroll
            for (int i = 0; i < 24; ++i) a[i] = bias;
            conv_acc<24, 25, 128>(g_wt_conv0, 256, xin, o, a);
#pragma unroll
            for (int i = 0; i < 24; ++i) {
                const int p = 25 + i;
                xoutP[o * PAD + p + 2 * (p / 7) + 10] = fmaxf(a[i], 0.0f);
            }
        }
    }
    __syncthreads();

    // ---- 4: zero inpP + h0P + h1P (xin is dead; xoutP untouched) ----
    for (int i = tid; i < 20979; i += 256) sm[i] = 0.0f;
    __syncthreads();

    // ---- 5: conv1 (128->128) + ReLU -> inpP channels 0..127 ----
    {
        const int o = tid & 127;
        const int half = tid >> 7;
        const float bias = b1[o];
        if (half == 0) {
            float a[25];
#pragma unroll
            for (int i = 0; i < 25; ++i) a[i] = bias;
            conv_acc<25, 0, 128>(g_wt_conv1, 128, xoutP, o, a);
#pragma unroll
            for (int i = 0; i < 25; ++i) {
                const int p = i;
                inpP[o * PAD + p + 2 * (p / 7) + 10] = fmaxf(a[i], 0.0f);
            }
        } else {
            float a[24];
#pragma unroll
            for (int i = 0; i < 24; ++i) a[i] = bias;
            conv_acc<24, 25, 128>(g_wt_conv1, 128, xoutP, o, a);
#pragma unroll
            for (int i = 0; i < 24; ++i) {
                const int p = 25 + i;
                inpP[o * PAD + p + 2 * (p / 7) + 10] = fmaxf(a[i], 0.0f);
            }
        }
    }
    __syncthreads();

    // ---- 6: zero c0,c1 (xoutP now dead); set v_p1 = v_first one-hot ----
    for (int i = tid; i < 6272; i += 256) c0s[i] = 0.0f;   // covers c0s and c1s (contiguous)
    if (tid == 0) {
        int v = first_vertex[s];                            // in [0, 48]
        int idx = v + 2 * (v / 7) + 10;
        inpP[129 * PAD + idx] = 1.0f;                       // v_pred1 = v_first
        inpP[130 * PAD + idx] = 1.0f;                       // v_first
    }
    __syncthreads();

    const float bias_g0 = bcx0[tid] + bch0[tid];
    const float bias_g1 = bcx1[tid] + bch1[tid];
    const int warp = tid >> 5, lane = tid & 31;

    for (int t = 0; t < STEPS; ++t) {
        // ---- layer0 gates: conv(inpP; cx0) + conv(h0P; ch0) ----
        {
            float a[49];
#pragma unroll
            for (int i = 0; i < 49; ++i) a[i] = bias_g0;
            conv_acc<49, 0, 256>(g_wt_cx0, 131, inpP, tid, a);
            conv_acc<49, 0, 256>(g_wt_ch0, 64, h0P, tid, a);
#pragma unroll
            for (int i = 0; i < 49; ++i) gsm[tid * 49 + i] = a[i];
        }
        __syncthreads();

        // ---- LSTM0 update ----
        for (int i = tid; i < 3136; i += 256) {
            int c = i / 49, p = i % 49;
            float ig = sigm(gsm[c * 49 + p]);
            float fg = sigm(gsm[(c + 64) * 49 + p]);
            float gg = tanhf(gsm[(c + 128) * 49 + p]);
            float og = sigm(gsm[(c + 192) * 49 + p]);
            float cy = fg * c0s[i] + ig * gg;
            c0s[i] = cy;
            h0P[c * PAD + p + 2 * (p / 7) + 10] = og * tanhf(cy);
        }
        __syncthreads();

        // ---- layer1 gates: conv(h0P; cx1) + conv(h1P; ch1) ----
        {
            float a[49];
#pragma unroll
            for (int i = 0; i < 49; ++i) a[i] = bias_g1;
            conv_acc<49, 0, 256>(g_wt_cx1, 64, h0P, tid, a);
            conv_acc<49, 0, 256>(g_wt_ch1, 64, h1P, tid, a);
#pragma unroll
            for (int i = 0; i < 49; ++i) gsm[tid * 49 + i] = a[i];
        }
        __syncthreads();

        // ---- LSTM1 update ----
        for (int i = tid; i < 3136; i += 256) {
            int c = i / 49, p = i % 49;
            float ig = sigm(gsm[c * 49 + p]);
            float fg = sigm(gsm[(c + 64) * 49 + p]);
            float gg = tanhf(gsm[(c + 128) * 49 + p]);
            float og = sigm(gsm[(c + 192) * 49 + p]);
            float cy = fg * c1s[i] + ig * gg;
            c1s[i] = cy;
            h1P[c * PAD + p + 2 * (p / 7) + 10] = og * tanhf(cy);
        }
        __syncthreads();

        // ---- fc: logits[50] = h1.flat @ fc_w.T + fc_b ----
        for (int o = warp; o < 50; o += 8) {
            float ssum = 0.0f;
            const float* wr = fcw + o * 3136;
            for (int j = lane; j < 3136; j += 32) {
                int c = j / 49, p = j % 49;
                ssum += wr[j] * h1P[c * PAD + p + 2 * (p / 7) + 10];
            }
#pragma unroll
            for (int d = 16; d; d >>= 1) ssum += __shfl_down_sync(0xffffffffu, ssum, d);
            if (lane == 0) lg[o] = ssum + fcb[o];
        }
        __syncthreads();

        // ---- emit logits; argmax (first-max wins, like jnp.argmax) ----
        if (tid < 50) out[((size_t)s * STEPS + t) * 50 + tid] = lg[tid];
        if (tid == 0) {
            int best = 0;
            float bv = lg[0];
#pragma unroll 1
            for (int o2 = 1; o2 < 50; ++o2) {
                float v = lg[o2];
                if (v > bv) { bv = v; best = o2; }
            }
            *predp = best;
        }
        __syncthreads();

        // ---- feedback: v_p2 <- v_p1 ; v_p1 <- one_hot(pred) (class 49 -> zeros) ----
        {
            int pr = *predp;
            if (tid < 49) {
                int idx = tid + 2 * (tid / 7) + 10;
                inpP[128 * PAD + idx] = inpP[129 * PAD + idx];
                inpP[129 * PAD + idx] = (pr == tid) ? 1.0f : 0.0f;
            }
        }
        __syncthreads();
    }
}

extern "C" void kernel_launch(void* const* d_in, const int* in_sizes, int n_in,
                              void* d_out, int out_size)
{
    const float* x    = (const float*)d_in[0];
    const int*   fv   = (const int*)  d_in[1];
    const float* w0   = (const float*)d_in[2];
    const float* b0   = (const float*)d_in[3];
    const float* w1   = (const float*)d_in[4];
    const float* b1   = (const float*)d_in[5];
    const float* wcx0 = (const float*)d_in[6];
    const float* bcx0 = (const float*)d_in[7];
    const float* wch0 = (const float*)d_in[8];
    const float* bch0 = (const float*)d_in[9];
    const float* wcx1 = (const float*)d_in[10];
    const float* bcx1 = (const float*)d_in[11];
    const float* wch1 = (const float*)d_in[12];
    const float* bch1 = (const float*)d_in[13];
    const float* fcw  = (const float*)d_in[14];
    const float* fcb  = (const float*)d_in[15];
    float* out = (float*)d_out;

    const int n = in_sizes[1];   // first_vertex element count = batch

    const int total_w = 128 * 2304 + 128 * 1152 + 256 * 1179 + 3 * 256 * 576;
    transpose_all<<<(total_w + 255) / 256, 256>>>(w0, w1, wcx0, wch0, wcx1, wch1);

    const int smem_bytes = SMEM_FLOATS * 4;
    cudaFuncSetAttribute(polyrnn_main, cudaFuncAttributeMaxDynamicSharedMemorySize, smem_bytes);
    polyrnn_main<<<n, 256, smem_bytes>>>(x, fv, b0, b1, bcx0, bch0, bcx1, bch1, fcw, fcb, out);
}

// round 3
// speedup vs baseline: 1.4185x; 1.4185x over previous
#include <cuda_runtime.h>
#include <math.h>

#define STEPS 9

// ---------------- packed pair weights (device globals; no allocation) ----
// layout: [(cpair*9 + k) * O + o] as float2 = (w[o][2cp][k], w[o][2cp+1][k])
__device__ float2 g_p_conv0[128 * 9 * 128];  // C=256 -> 128 cp, O=128
__device__ float2 g_p_conv1[ 64 * 9 * 128];  // C=128 -> 64 cp,  O=128
__device__ float2 g_p_cx0 [ 66 * 9 * 256];   // C=131 -> pad 132 -> 66 cp, O=256
__device__ float2 g_p_ch0 [ 32 * 9 * 256];   // C=64  -> 32 cp,  O=256
__device__ float2 g_p_cx1 [ 32 * 9 * 256];
__device__ float2 g_p_ch1 [ 32 * 9 * 256];

__global__ void pack_weights(const float* __restrict__ w0, const float* __restrict__ w1,
                             const float* __restrict__ wcx0, const float* __restrict__ wch0,
                             const float* __restrict__ wcx1, const float* __restrict__ wch1)
{
    int i = blockIdx.x * blockDim.x + threadIdx.x;
    const int s0 = 128 * 9 * 128, s1 = 64 * 9 * 128, s2 = 66 * 9 * 256, s3 = 32 * 9 * 256;
    if (i < s0) {
        int o = i % 128, ck = i / 128, cp = ck / 9, k = ck % 9;
        g_p_conv0[i] = make_float2(w0[(o * 256 + 2 * cp) * 9 + k],
                                   w0[(o * 256 + 2 * cp + 1) * 9 + k]);
        return;
    }
    i -= s0;
    if (i < s1) {
        int o = i % 128, ck = i / 128, cp = ck / 9, k = ck % 9;
        g_p_conv1[i] = make_float2(w1[(o * 128 + 2 * cp) * 9 + k],
                                   w1[(o * 128 + 2 * cp + 1) * 9 + k]);
        return;
    }
    i -= s1;
    if (i < s2) {
        int o = i % 256, ck = i / 256, cp = ck / 9, k = ck % 9;
        int c0 = 2 * cp, c1 = 2 * cp + 1;
        float a = (c0 < 131) ? wcx0[(o * 131 + c0) * 9 + k] : 0.0f;
        float b = (c1 < 131) ? wcx0[(o * 131 + c1) * 9 + k] : 0.0f;
        g_p_cx0[i] = make_float2(a, b);
        return;
    }
    i -= s2;
    if (i < s3) {
        int o = i % 256, ck = i / 256, cp = ck / 9, k = ck % 9;
        g_p_ch0[i] = make_float2(wch0[(o * 64 + 2 * cp) * 9 + k],
                                 wch0[(o * 64 + 2 * cp + 1) * 9 + k]);
        return;
    }
    i -= s3;
    if (i < s3) {
        int o = i % 256, ck = i / 256, cp = ck / 9, k = ck % 9;
        g_p_cx1[i] = make_float2(wcx1[(o * 64 + 2 * cp) * 9 + k],
                                 wcx1[(o * 64 + 2 * cp + 1) * 9 + k]);
        return;
    }
    i -= s3;
    if (i < s3) {
        int o = i % 256, ck = i / 256, cp = ck / 9, k = ck % 9;
        g_p_ch1[i] = make_float2(wch1[(o * 64 + 2 * cp) * 9 + k],
                                 wch1[(o * 64 + 2 * cp + 1) * 9 + k]);
        return;
    }
}

// ---------------- packed fp32x2 helpers ----------------
__device__ __forceinline__ void ffma2(unsigned long long& d, unsigned long long a,
                                      unsigned long long b)
{
    asm("fma.rn.f32x2 %0, %1, %2, %0;" : "+l"(d) : "l"(a), "l"(b));
}
__device__ __forceinline__ unsigned long long pack2(float lo, float hi)
{
    unsigned long long r;
    asm("mov.b64 %0, {%1, %2};" : "=l"(r) : "f"(lo), "f"(hi));
    return r;
}
__device__ __forceinline__ float fold2(unsigned long long v)
{
    float lo, hi;
    asm("mov.b64 {%0, %1}, %2;" : "=f"(lo), "=f"(hi) : "l"(v));
    return lo + hi;
}
__device__ __forceinline__ int ppad(int p) { return p + 2 * (p / 7) + 10; }
__device__ __forceinline__ float sigm(float v) { return 1.0f / (1.0f + expf(-v)); }

// 3x3 SAME conv over channel-pair-interleaved padded planes.
// plane layout: [cpair][pp(0..80)][2 floats] -> 8B-aligned pair at u64 index cp*81+pp.
// Thread owns out-channel o, output rows [Y0, Y0+NR). acc = NR*7 packed partial sums.
template <int NR, int Y0>
__device__ __forceinline__ void conv_pair(const float2* __restrict__ W, const int CP,
                                          const int Ostride, const float* __restrict__ plane,
                                          const int o, unsigned long long* acc)
{
    const unsigned long long* Pl = (const unsigned long long*)plane;
    const unsigned long long* Wp = (const unsigned long long*)W;
    unsigned long long wA[9];
#pragma unroll
    for (int k = 0; k < 9; ++k) wA[k] = __ldg(Wp + (size_t)k * Ostride + o);

    for (int cp = 0; cp < CP; ++cp) {
        unsigned long long wB[9];
        const int cpn = (cp + 1 < CP) ? cp + 1 : cp;
#pragma unroll
        for (int k = 0; k < 9; ++k) wB[k] = __ldg(Wp + ((size_t)cpn * 9 + k) * Ostride + o);

        const unsigned long long* pb = Pl + cp * 81;
        unsigned long long win[3][9];
#pragma unroll
        for (int j = 0; j < 9; ++j) win[Y0 % 3][j] = pb[Y0 * 9 + j];
#pragma unroll
        for (int j = 0; j < 9; ++j) win[(Y0 + 1) % 3][j] = pb[(Y0 + 1) * 9 + j];

#pragma unroll
        for (int ry = 0; ry < NR; ++ry) {
            const int rl = Y0 + ry + 2;
#pragma unroll
            for (int j = 0; j < 9; ++j) win[rl % 3][j] = pb[rl * 9 + j];
#pragma unroll
            for (int ky = 0; ky < 3; ++ky) {
                const int rr = (Y0 + ry + ky) % 3;
#pragma unroll
                for (int x = 0; x < 7; ++x) {
#pragma unroll
                    for (int kx = 0; kx < 3; ++kx)
                        ffma2(acc[ry * 7 + x], wA[ky * 3 + kx], win[rr][x + kx]);
                }
            }
        }
#pragma unroll
        for (int k = 0; k < 9; ++k) wA[k] = wB[k];
    }
}

// ---------------- SMEM layout (floats) ----------------
// recurrence:
//   inpP @ 0     : 66cp*162 = 10692   (x feats cp0..63, cp64=(v_p2,v_p1), cp65=(v_first,0))
//   h0P  @ 10692 : 32cp*162 = 5184
//   h1P  @ 15876 : 5184
//   c0   @ 21060 : 3136
//   c1   @ 24196 : 3136
//   gsm  @ 27332 : 12544
//   lg   @ 39876 : 50 ; pred @ 39926
// phase A overlays: xin @ 0 (128cp*162=20736), xoutP @ 21060 (64cp*162=10368)
#define SM_H0   10692
#define SM_H1   15876
#define SM_C0   21060
#define SM_C1   24196
#define SM_G    27332
#define SM_LG   39876
#define SM_PRED 39926
#define SMEM_FLOATS 39936

__global__ __launch_bounds__(256, 1)
void polyrnn_main(const float* __restrict__ x, const int* __restrict__ first_vertex,
                  const float* __restrict__ b0, const float* __restrict__ b1,
                  const float* __restrict__ bcx0, const float* __restrict__ bch0,
                  const float* __restrict__ bcx1, const float* __restrict__ bch1,
                  const float* __restrict__ fcw, const float* __restrict__ fcb,
                  float* __restrict__ out)
{
    extern __shared__ float sm[];
    float* inpP  = sm;
    float* h0P   = sm + SM_H0;
    float* h1P   = sm + SM_H1;
    float* c0s   = sm + SM_C0;
    float* c1s   = sm + SM_C1;
    float* gsm   = sm + SM_G;
    float* lg    = sm + SM_LG;
    int*   predp = (int*)(sm + SM_PRED);
    float* xin   = sm;          // phase A
    float* xoutP = sm + SM_C0;  // phase A

    const int s   = blockIdx.x;
    const int tid = threadIdx.x;

    // ---- 1: zero xin + xoutP regions ----
    for (int i = tid; i < 31428; i += 256) sm[i] = 0.0f;
    __syncthreads();

    // ---- 2: load x into pair-interleaved padded planes ----
    const float* xs = x + (size_t)s * (256 * 49);
    for (int i = tid; i < 256 * 49; i += 256) {
        int c = i / 49, p = i % 49;
        xin[(c >> 1) * 162 + ppad(p) * 2 + (c & 1)] = xs[i];
    }
    __syncthreads();

    // ---- 3: conv0 (256->128) + ReLU -> xoutP ----
    {
        const int o = tid & 127, half = tid >> 7;
        const unsigned long long binit = pack2(b0[o], 0.0f);
        if (half == 0) {
            unsigned long long a[28];
#pragma unroll
            for (int i = 0; i < 28; ++i) a[i] = binit;
            conv_pair<4, 0>(g_p_conv0, 128, 128, xin, o, a);
#pragma unroll
            for (int i = 0; i < 28; ++i) {
                const int p = i;  // rows 0..3
                xoutP[(o >> 1) * 162 + ppad(p) * 2 + (o & 1)] = fmaxf(fold2(a[i]), 0.0f);
            }
        } else {
            unsigned long long a[21];
#pragma unroll
            for (int i = 0; i < 21; ++i) a[i] = binit;
            conv_pair<3, 4>(g_p_conv0, 128, 128, xin, o, a);
#pragma unroll
            for (int i = 0; i < 21; ++i) {
                const int p = 28 + i;  // rows 4..6
                xoutP[(o >> 1) * 162 + ppad(p) * 2 + (o & 1)] = fmaxf(fold2(a[i]), 0.0f);
            }
        }
    }
    __syncthreads();

    // ---- 4: zero inpP + h0P + h1P (xin dead; xoutP untouched) ----
    for (int i = tid; i < SM_C0; i += 256) sm[i] = 0.0f;
    __syncthreads();

    // ---- 5: conv1 (128->128) + ReLU -> inpP channels 0..127 ----
    {
        const int o = tid & 127, half = tid >> 7;
        const unsigned long long binit = pack2(b1[o], 0.0f);
        if (half == 0) {
            unsigned long long a[28];
#pragma unroll
            for (int i = 0; i < 28; ++i) a[i] = binit;
            conv_pair<4, 0>(g_p_conv1, 64, 128, xoutP, o, a);
#pragma unroll
            for (int i = 0; i < 28; ++i) {
                const int p = i;
                inpP[(o >> 1) * 162 + ppad(p) * 2 + (o & 1)] = fmaxf(fold2(a[i]), 0.0f);
            }
        } else {
            unsigned long long a[21];
#pragma unroll
            for (int i = 0; i < 21; ++i) a[i] = binit;
            conv_pair<3, 4>(g_p_conv1, 64, 128, xoutP, o, a);
#pragma unroll
            for (int i = 0; i < 21; ++i) {
                const int p = 28 + i;
                inpP[(o >> 1) * 162 + ppad(p) * 2 + (o & 1)] = fmaxf(fold2(a[i]), 0.0f);
            }
        }
    }
    __syncthreads();

    // ---- 6: zero c0,c1 (xoutP dead); vertex one-hots ----
    for (int i = tid; i < 6272; i += 256) c0s[i] = 0.0f;
    if (tid == 0) {
        int v = first_vertex[s];           // in [0,48]
        int a2 = ppad(v) * 2;
        inpP[64 * 162 + a2 + 1] = 1.0f;    // v_pred1 (c=129)
        inpP[65 * 162 + a2 + 0] = 1.0f;    // v_first (c=130); c=131 lane stays 0
    }
    __syncthreads();

    const float bias_g0 = bcx0[tid] + bch0[tid];
    const float bias_g1 = bcx1[tid] + bch1[tid];
    const int warp = tid >> 5, lane = tid & 31;

    for (int t = 0; t < STEPS; ++t) {
        // ---- layer0 gates ----
        {
            unsigned long long a[49];
            const unsigned long long binit = pack2(bias_g0, 0.0f);
#pragma unroll
            for (int i = 0; i < 49; ++i) a[i] = binit;
            conv_pair<7, 0>(g_p_cx0, 66, 256, inpP, tid, a);
            conv_pair<7, 0>(g_p_ch0, 32, 256, h0P, tid, a);
#pragma unroll
            for (int i = 0; i < 49; ++i) gsm[tid * 49 + i] = fold2(a[i]);
        }
        __syncthreads();

        // ---- LSTM0 ----
        for (int i = tid; i < 3136; i += 256) {
            int c = i / 49, p = i % 49;
            float ig = sigm(gsm[c * 49 + p]);
            float fg = sigm(gsm[(c + 64) * 49 + p]);
            float gg = tanhf(gsm[(c + 128) * 49 + p]);
            float og = sigm(gsm[(c + 192) * 49 + p]);
            float cy = fg * c0s[i] + ig * gg;
            c0s[i] = cy;
            h0P[(c >> 1) * 162 + ppad(p) * 2 + (c & 1)] = og * tanhf(cy);
        }
        __syncthreads();

        // ---- layer1 gates ----
        {
            unsigned long long a[49];
            const unsigned long long binit = pack2(bias_g1, 0.0f);
#pragma unroll
            for (int i = 0; i < 49; ++i) a[i] = binit;
            conv_pair<7, 0>(g_p_cx1, 32, 256, h0P, tid, a);
            conv_pair<7, 0>(g_p_ch1, 32, 256, h1P, tid, a);
#pragma unroll
            for (int i = 0; i < 49; ++i) gsm[tid * 49 + i] = fold2(a[i]);
        }
        __syncthreads();

        // ---- LSTM1 ----
        for (int i = tid; i < 3136; i += 256) {
            int c = i / 49, p = i % 49;
            float ig = sigm(gsm[c * 49 + p]);
            float fg = sigm(gsm[(c + 64) * 49 + p]);
            float gg = tanhf(gsm[(c + 128) * 49 + p]);
            float og = sigm(gsm[(c + 192) * 49 + p]);
            float cy = fg * c1s[i] + ig * gg;
            c1s[i] = cy;
            h1P[(c >> 1) * 162 + ppad(p) * 2 + (c & 1)] = og * tanhf(cy);
        }
        __syncthreads();

        // ---- fc: logits[50] ----
        for (int o = warp; o < 50; o += 8) {
            float ssum = 0.0f;
            const float* wr = fcw + o * 3136;
            for (int j = lane; j < 3136; j += 32) {
                int c = j / 49, p = j % 49;
                ssum += wr[j] * h1P[(c >> 1) * 162 + ppad(p) * 2 + (c & 1)];
            }
#pragma unroll
            for (int d = 16; d; d >>= 1) ssum += __shfl_down_sync(0xffffffffu, ssum, d);
            if (lane == 0) lg[o] = ssum + fcb[o];
        }
        __syncthreads();

        // ---- emit + argmax (first max wins) ----
        if (tid < 50) out[((size_t)s * STEPS + t) * 50 + tid] = lg[tid];
        if (tid == 0) {
            int best = 0;
            float bv = lg[0];
#pragma unroll 1
            for (int o2 = 1; o2 < 50; ++o2) {
                float v = lg[o2];
                if (v > bv) { bv = v; best = o2; }
            }
            *predp = best;
        }
        __syncthreads();

        // ---- feedback: v_p2 <- v_p1 ; v_p1 <- one_hot(pred) (49 == EOS -> zeros) ----
        {
            int pr = *predp;
            if (tid < 49) {
                int a2 = ppad(tid) * 2;
                inpP[64 * 162 + a2 + 0] = inpP[64 * 162 + a2 + 1];
                inpP[64 * 162 + a2 + 1] = (pr == tid) ? 1.0f : 0.0f;
            }
        }
        __syncthreads();
    }
}

extern "C" void kernel_launch(void* const* d_in, const int* in_sizes, int n_in,
                              void* d_out, int out_size)
{
    const float* x    = (const float*)d_in[0];
    const int*   fv   = (const int*)  d_in[1];
    const float* w0   = (const float*)d_in[2];
    const float* b0   = (const float*)d_in[3];
    const float* w1   = (const float*)d_in[4];
    const float* b1   = (const float*)d_in[5];
    const float* wcx0 = (const float*)d_in[6];
    const float* bcx0 = (const float*)d_in[7];
    const float* wch0 = (const float*)d_in[8];
    const float* bch0 = (const float*)d_in[9];
    const float* wcx1 = (const float*)d_in[10];
    const float* bcx1 = (const float*)d_in[11];
    const float* wch1 = (const float*)d_in[12];
    const float* bch1 = (const float*)d_in[13];
    const float* fcw  = (const float*)d_in[14];
    const float* fcb  = (const float*)d_in[15];
    float* out = (float*)d_out;

    const int n = in_sizes[1];  // batch

    const int total = 128 * 9 * 128 + 64 * 9 * 128 + 66 * 9 * 256 + 3 * 32 * 9 * 256;
    pack_weights<<<(total + 255) / 256, 256>>>(w0, w1, wcx0, wch0, wcx1, wch1);

    const int smem_bytes = SMEM_FLOATS * 4;
    cudaFuncSetAttribute(polyrnn_main, cudaFuncAttributeMaxDynamicSharedMemorySize, smem_bytes);
    polyrnn_main<<<n, 256, smem_bytes>>>(x, fv, b0, b1, bcx0, bch0, bcx1, bch1, fcw, fcb, out);
}

// round 4
// speedup vs baseline: 1.8545x; 1.3073x over previous
#include <cuda_runtime.h>
#include <math.h>

#define STEPS 9

// ---------------- packed pair weights (device globals; no allocation) ----
// layout: [(cpair*9 + k) * O + o] as float2
__device__ float2 g_p_conv0[128 * 9 * 128];  // C=256 -> 128 cp, O=128
__device__ float2 g_p_conv1[ 64 * 9 * 128];  // C=128 -> 64 cp,  O=128
// cx0 cp order: cp0..63 = x channel pairs (2cp,2cp+1); cp64 = (ch130 v_first, 0);
//               cp65 = (ch128 v_p2, ch129 v_p1)  [the only dynamic pair]
__device__ float2 g_p_cx0 [ 66 * 9 * 256];
__device__ float2 g_p_ch0 [ 32 * 9 * 256];   // C=64 -> 32 cp, O=256
__device__ float2 g_p_cx1 [ 32 * 9 * 256];
__device__ float2 g_p_ch1 [ 32 * 9 * 256];

__global__ void pack_weights(const float* __restrict__ w0, const float* __restrict__ w1,
                             const float* __restrict__ wcx0, const float* __restrict__ wch0,
                             const float* __restrict__ wcx1, const float* __restrict__ wch1)
{
    int i = blockIdx.x * blockDim.x + threadIdx.x;
    const int s0 = 128 * 9 * 128, s1 = 64 * 9 * 128, s2 = 66 * 9 * 256, s3 = 32 * 9 * 256;
    if (i < s0) {
        int o = i % 128, ck = i / 128, cp = ck / 9, k = ck % 9;
        g_p_conv0[i] = make_float2(w0[(o * 256 + 2 * cp) * 9 + k],
                                   w0[(o * 256 + 2 * cp + 1) * 9 + k]);
        return;
    }
    i -= s0;
    if (i < s1) {
        int o = i % 128, ck = i / 128, cp = ck / 9, k = ck % 9;
        g_p_conv1[i] = make_float2(w1[(o * 128 + 2 * cp) * 9 + k],
                                   w1[(o * 128 + 2 * cp + 1) * 9 + k]);
        return;
    }
    i -= s1;
    if (i < s2) {
        int o = i % 256, ck = i / 256, cp = ck / 9, k = ck % 9;
        float a, b;
        if (cp < 64)      { a = wcx0[(o * 131 + 2 * cp) * 9 + k];
                            b = wcx0[(o * 131 + 2 * cp + 1) * 9 + k]; }
        else if (cp == 64){ a = wcx0[(o * 131 + 130) * 9 + k]; b = 0.0f; }
        else              { a = wcx0[(o * 131 + 128) * 9 + k];
                            b = wcx0[(o * 131 + 129) * 9 + k]; }
        g_p_cx0[i] = make_float2(a, b);
        return;
    }
    i -= s2;
    if (i < s3) {
        int o = i % 256, ck = i / 256, cp = ck / 9, k = ck % 9;
        g_p_ch0[i] = make_float2(wch0[(o * 64 + 2 * cp) * 9 + k],
                                 wch0[(o * 64 + 2 * cp + 1) * 9 + k]);
        return;
    }
    i -= s3;
    if (i < s3) {
        int o = i % 256, ck = i / 256, cp = ck / 9, k = ck % 9;
        g_p_cx1[i] = make_float2(wcx1[(o * 64 + 2 * cp) * 9 + k],
                                 wcx1[(o * 64 + 2 * cp + 1) * 9 + k]);
        return;
    }
    i -= s3;
    if (i < s3) {
        int o = i % 256, ck = i / 256, cp = ck / 9, k = ck % 9;
        g_p_ch1[i] = make_float2(wch1[(o * 64 + 2 * cp) * 9 + k],
                                 wch1[(o * 64 + 2 * cp + 1) * 9 + k]);
        return;
    }
}

// ---------------- packed fp32x2 helpers ----------------
__device__ __forceinline__ void ffma2(unsigned long long& d, unsigned long long a,
                                      unsigned long long b)
{
    asm("fma.rn.f32x2 %0, %1, %2, %0;" : "+l"(d) : "l"(a), "l"(b));
}
__device__ __forceinline__ unsigned long long pack2(float lo, float hi)
{
    unsigned long long r;
    asm("mov.b64 %0, {%1, %2};" : "=l"(r) : "f"(lo), "f"(hi));
    return r;
}
__device__ __forceinline__ float fold2(unsigned long long v)
{
    float lo, hi;
    asm("mov.b64 {%0, %1}, %2;" : "=f"(lo), "=f"(hi) : "l"(v));
    return lo + hi;
}
__device__ __forceinline__ int ppad(int p) { return p + 2 * (p / 7) + 10; }
__device__ __forceinline__ float sigm(float v) { return 1.0f / (1.0f + expf(-v)); }

// 3x3 SAME conv over channel-pair-interleaved padded planes.
// plane: [cp][pp 0..80][2 floats] -> u64 at cp*81+pp. Thread owns out-ch o,
// output rows [Y0, Y0+NR). acc = NR*7 packed partials. Double-buffered weights.
template <int NR, int Y0>
__device__ __forceinline__ void conv_pair(const float2* __restrict__ W, const int CP,
                                          const int Ostride, const float* __restrict__ plane,
                                          const int o, unsigned long long* acc)
{
    const unsigned long long* Pl = (const unsigned long long*)plane;
    const unsigned long long* Wp = (const unsigned long long*)W;
    unsigned long long wA[9];
#pragma unroll
    for (int k = 0; k < 9; ++k) wA[k] = __ldg(Wp + (size_t)k * Ostride + o);

    for (int cp = 0; cp < CP; ++cp) {
        unsigned long long wB[9];
        const int cpn = (cp + 1 < CP) ? cp + 1 : cp;
#pragma unroll
        for (int k = 0; k < 9; ++k) wB[k] = __ldg(Wp + ((size_t)cpn * 9 + k) * Ostride + o);

        const unsigned long long* pb = Pl + cp * 81;
        unsigned long long win[3][9];
#pragma unroll
        for (int j = 0; j < 9; ++j) win[Y0 % 3][j] = pb[Y0 * 9 + j];
#pragma unroll
        for (int j = 0; j < 9; ++j) win[(Y0 + 1) % 3][j] = pb[(Y0 + 1) * 9 + j];

#pragma unroll
        for (int ry = 0; ry < NR; ++ry) {
            const int rl = Y0 + ry + 2;
#pragma unroll
            for (int j = 0; j < 9; ++j) win[rl % 3][j] = pb[rl * 9 + j];
#pragma unroll
            for (int ky = 0; ky < 3; ++ky) {
                const int rr = (Y0 + ry + ky) % 3;
#pragma unroll
                for (int x = 0; x < 7; ++x) {
#pragma unroll
                    for (int kx = 0; kx < 3; ++kx)
                        ffma2(acc[ry * 7 + x], wA[ky * 3 + kx], win[rr][x + kx]);
                }
            }
        }
#pragma unroll
        for (int k = 0; k < 9; ++k) wA[k] = wB[k];
    }
}

// ---------------- SMEM layout (floats) ----------------
// recurrence:
//   h0P  @ 0     : 32cp*162 = 5184
//   h1P  @ 5184  : 5184
//   c0   @ 10368 : 3136
//   c1   @ 13504 : 3136
//   gsm  @ 16640 : 12544
//   gxc  @ 29184 : 12544    (const gates incl. bias_g0)
//   vtxP @ 41728 : 162      ((v_p2, v_p1) padded pair plane)
//   lg   @ 41890 : 50 ; pred @ 41940
// phase A overlays:
//   xin  @ 0     : 128cp*162 = 20736
//   xoutP@ 29184 : 64cp*162  = 10368   (dead before gxc written)
//   x2P  @ 0     : 65cp*162  = 10530   (conv1 out + v_first plane @cp64)
#define SM_H0   0
#define SM_H1   5184
#define SM_C0   10368
#define SM_C1   13504
#define SM_G    16640
#define SM_GXC  29184
#define SM_VTX  41728
#define SM_LG   41890
#define SM_PRED 41940
#define SMEM_FLOATS 41952

__global__ __launch_bounds__(256, 1)
void polyrnn_main(const float* __restrict__ x, const int* __restrict__ first_vertex,
                  const float* __restrict__ b0, const float* __restrict__ b1,
                  const float* __restrict__ bcx0, const float* __restrict__ bch0,
                  const float* __restrict__ bcx1, const float* __restrict__ bch1,
                  const float* __restrict__ fcw, const float* __restrict__ fcb,
                  float* __restrict__ out)
{
    extern __shared__ float sm[];
    float* h0P   = sm + SM_H0;
    float* h1P   = sm + SM_H1;
    float* c0s   = sm + SM_C0;
    float* c1s   = sm + SM_C1;
    float* gsm   = sm + SM_G;
    float* gxc   = sm + SM_GXC;
    float* vtxP  = sm + SM_VTX;
    float* lg    = sm + SM_LG;
    int*   predp = (int*)(sm + SM_PRED);
    float* xin   = sm;            // phase A
    float* xoutP = sm + SM_GXC;   // phase A (overlays gxc region; dead before gxc)
    float* x2P   = sm;            // phase A (overlays xin after conv0)

    const int s   = blockIdx.x;
    const int tid = threadIdx.x;

    // ---- 1: zero xin + xoutP regions (borders must be 0) ----
    for (int i = tid; i < SM_GXC + 10368; i += 256) sm[i] = 0.0f;
    __syncthreads();

    // ---- 2: load x into pair-interleaved padded planes ----
    const float* xs = x + (size_t)s * (256 * 49);
    for (int i = tid; i < 256 * 49; i += 256) {
        int c = i / 49, p = i % 49;
        xin[(c >> 1) * 162 + ppad(p) * 2 + (c & 1)] = xs[i];
    }
    __syncthreads();

    // ---- 3: conv0 (256->128) + ReLU -> xoutP ----
    {
        const int o = tid & 127, half = tid >> 7;
        const unsigned long long binit = pack2(b0[o], 0.0f);
        if (half == 0) {
            unsigned long long a[28];
#pragma unroll
            for (int i = 0; i < 28; ++i) a[i] = binit;
            conv_pair<4, 0>(g_p_conv0, 128, 128, xin, o, a);
#pragma unroll
            for (int i = 0; i < 28; ++i)
                xoutP[(o >> 1) * 162 + ppad(i) * 2 + (o & 1)] = fmaxf(fold2(a[i]), 0.0f);
        } else {
            unsigned long long a[21];
#pragma unroll
            for (int i = 0; i < 21; ++i) a[i] = binit;
            conv_pair<3, 4>(g_p_conv0, 128, 128, xin, o, a);
#pragma unroll
            for (int i = 0; i < 21; ++i)
                xoutP[(o >> 1) * 162 + ppad(28 + i) * 2 + (o & 1)] = fmaxf(fold2(a[i]), 0.0f);
        }
    }
    __syncthreads();

    // ---- 4: conv1 (128->128) + ReLU -> x2P cps 0..63 (overlays xin; borders still 0) ----
    {
        const int o = tid & 127, half = tid >> 7;
        const unsigned long long binit = pack2(b1[o], 0.0f);
        if (half == 0) {
            unsigned long long a[28];
#pragma unroll
            for (int i = 0; i < 28; ++i) a[i] = binit;
            conv_pair<4, 0>(g_p_conv1, 64, 128, xoutP, o, a);
#pragma unroll
            for (int i = 0; i < 28; ++i)
                x2P[(o >> 1) * 162 + ppad(i) * 2 + (o & 1)] = fmaxf(fold2(a[i]), 0.0f);
        } else {
            unsigned long long a[21];
#pragma unroll
            for (int i = 0; i < 21; ++i) a[i] = binit;
            conv_pair<3, 4>(g_p_conv1, 64, 128, xoutP, o, a);
#pragma unroll
            for (int i = 0; i < 21; ++i)
                x2P[(o >> 1) * 162 + ppad(28 + i) * 2 + (o & 1)] = fmaxf(fold2(a[i]), 0.0f);
        }
    }
    __syncthreads();

    // ---- 5: build v_first plane at x2P cp64 (zero stale x data, set one-hot) ----
    if (tid < 162) x2P[64 * 162 + tid] = 0.0f;
    __syncthreads();
    if (tid == 0) {
        int v = first_vertex[s];                 // [0,48]
        x2P[64 * 162 + ppad(v) * 2 + 0] = 1.0f;  // (v_first, 0) pair, lo lane
    }
    __syncthreads();

    // ---- 6: const-gate precompute: gxc = bias_g0 + conv(x2P cps0..64; cx0) ----
    {
        const float bg0 = bcx0[tid] + bch0[tid];
        const unsigned long long binit = pack2(bg0, 0.0f);
        {
            unsigned long long a[28];
#pragma unroll
            for (int i = 0; i < 28; ++i) a[i] = binit;
            conv_pair<4, 0>(g_p_cx0, 65, 256, x2P, tid, a);
#pragma unroll
            for (int i = 0; i < 28; ++i) gxc[tid * 49 + i] = fold2(a[i]);
        }
        {
            unsigned long long a[21];
#pragma unroll
            for (int i = 0; i < 21; ++i) a[i] = pack2(0.0f, 0.0f);
            conv_pair<3, 4>(g_p_cx0, 65, 256, x2P, tid, a);
#pragma unroll
            for (int i = 0; i < 21; ++i) gxc[tid * 49 + 28 + i] = bg0 + fold2(a[i]);
        }
    }
    __syncthreads();

    // ---- 7: zero h0,h1,c0,c1 (x2P dead) + vtxP; init v_p1 = v_first one-hot ----
    for (int i = tid; i < SM_G; i += 256) sm[i] = 0.0f;
    if (tid < 162) vtxP[tid] = 0.0f;
    __syncthreads();
    if (tid == 0) {
        int v = first_vertex[s];
        vtxP[ppad(v) * 2 + 1] = 1.0f;            // (v_p2, v_p1): hi lane = v_p1
    }
    __syncthreads();

    const float bias_g1 = bcx1[tid] + bch1[tid];
    const float2* cx0_dyn = g_p_cx0 + 65 * 9 * 256;   // dynamic (v_p2, v_p1) pair weights
    const int warp = tid >> 5, lane = tid & 31;

    for (int t = 0; t < STEPS; ++t) {
        // ---- layer0 gates: gxc + conv(vtxP; cx0_dyn) + conv(h0P; ch0) ----
        {
            unsigned long long a[28];
#pragma unroll
            for (int i = 0; i < 28; ++i) a[i] = pack2(gxc[tid * 49 + i], 0.0f);
            conv_pair<4, 0>(cx0_dyn, 1, 256, vtxP, tid, a);
            conv_pair<4, 0>(g_p_ch0, 32, 256, h0P, tid, a);
#pragma unroll
            for (int i = 0; i < 28; ++i) gsm[tid * 49 + i] = fold2(a[i]);
        }
        {
            unsigned long long a[21];
#pragma unroll
            for (int i = 0; i < 21; ++i) a[i] = pack2(gxc[tid * 49 + 28 + i], 0.0f);
            conv_pair<3, 4>(cx0_dyn, 1, 256, vtxP, tid, a);
            conv_pair<3, 4>(g_p_ch0, 32, 256, h0P, tid, a);
#pragma unroll
            for (int i = 0; i < 21; ++i) gsm[tid * 49 + 28 + i] = fold2(a[i]);
        }
        __syncthreads();

        // ---- LSTM0 ----
        for (int i = tid; i < 3136; i += 256) {
            int c = i / 49, p = i % 49;
            float ig = sigm(gsm[c * 49 + p]);
            float fg = sigm(gsm[(c + 64) * 49 + p]);
            float gg = tanhf(gsm[(c + 128) * 49 + p]);
            float og = sigm(gsm[(c + 192) * 49 + p]);
            float cy = fg * c0s[i] + ig * gg;
            c0s[i] = cy;
            h0P[(c >> 1) * 162 + ppad(p) * 2 + (c & 1)] = og * tanhf(cy);
        }
        __syncthreads();

        // ---- layer1 gates: conv(h0P; cx1) + conv(h1P; ch1) ----
        {
            unsigned long long a[28];
            const unsigned long long binit = pack2(bias_g1, 0.0f);
#pragma unroll
            for (int i = 0; i < 28; ++i) a[i] = binit;
            conv_pair<4, 0>(g_p_cx1, 32, 256, h0P, tid, a);
            conv_pair<4, 0>(g_p_ch1, 32, 256, h1P, tid, a);
#pragma unroll
            for (int i = 0; i < 28; ++i) gsm[tid * 49 + i] = fold2(a[i]);
        }
        {
            unsigned long long a[21];
            const unsigned long long binit = pack2(bias_g1, 0.0f);
#pragma unroll
            for (int i = 0; i < 21; ++i) a[i] = binit;
            conv_pair<3, 4>(g_p_cx1, 32, 256, h0P, tid, a);
            conv_pair<3, 4>(g_p_ch1, 32, 256, h1P, tid, a);
#pragma unroll
            for (int i = 0; i < 21; ++i) gsm[tid * 49 + 28 + i] = fold2(a[i]);
        }
        __syncthreads();

        // ---- LSTM1 ----
        for (int i = tid; i < 3136; i += 256) {
            int c = i / 49, p = i % 49;
            float ig = sigm(gsm[c * 49 + p]);
            float fg = sigm(gsm[(c + 64) * 49 + p]);
            float gg = tanhf(gsm[(c + 128) * 49 + p]);
            float og = sigm(gsm[(c + 192) * 49 + p]);
            float cy = fg * c1s[i] + ig * gg;
            c1s[i] = cy;
            h1P[(c >> 1) * 162 + ppad(p) * 2 + (c & 1)] = og * tanhf(cy);
        }
        __syncthreads();

        // ---- fc: logits[50] ----
        for (int o = warp; o < 50; o += 8) {
            float ssum = 0.0f;
            const float* wr = fcw + o * 3136;
            for (int j = lane; j < 3136; j += 32) {
                int c = j / 49, p = j % 49;
                ssum += wr[j] * h1P[(c >> 1) * 162 + ppad(p) * 2 + (c & 1)];
            }
#pragma unroll
            for (int d = 16; d; d >>= 1) ssum += __shfl_down_sync(0xffffffffu, ssum, d);
            if (lane == 0) lg[o] = ssum + fcb[o];
        }
        __syncthreads();

        // ---- emit + argmax (first max wins) ----
        if (tid < 50) out[((size_t)s * STEPS + t) * 50 + tid] = lg[tid];
        if (tid == 0) {
            int best = 0;
            float bv = lg[0];
#pragma unroll 1
            for (int o2 = 1; o2 < 50; ++o2) {
                float v = lg[o2];
                if (v > bv) { bv = v; best = o2; }
            }
            *predp = best;
        }
        __syncthreads();

        // ---- feedback: (v_p2, v_p1) <- (v_p1, one_hot(pred)); class 49 -> zeros ----
        {
            int pr = *predp;
            if (tid < 49) {
                int a2 = ppad(tid) * 2;
                vtxP[a2 + 0] = vtxP[a2 + 1];
                vtxP[a2 + 1] = (pr == tid) ? 1.0f : 0.0f;
            }
        }
        __syncthreads();
    }
}

extern "C" void kernel_launch(void* const* d_in, const int* in_sizes, int n_in,
                              void* d_out, int out_size)
{
    const float* x    = (const float*)d_in[0];
    const int*   fv   = (const int*)  d_in[1];
    const float* w0   = (const float*)d_in[2];
    const float* b0   = (const float*)d_in[3];
    const float* w1   = (const float*)d_in[4];
    const float* b1   = (const float*)d_in[5];
    const float* wcx0 = (const float*)d_in[6];
    const float* bcx0 = (const float*)d_in[7];
    const float* wch0 = (const float*)d_in[8];
    const float* bch0 = (const float*)d_in[9];
    const float* wcx1 = (const float*)d_in[10];
    const float* bcx1 = (const float*)d_in[11];
    const float* wch1 = (const float*)d_in[12];
    const float* bch1 = (const float*)d_in[13];
    const float* fcw  = (const float*)d_in[14];
    const float* fcb  = (const float*)d_in[15];
    float* out = (float*)d_out;

    const int n = in_sizes[1];  // batch

    const int total = 128 * 9 * 128 + 64 * 9 * 128 + 66 * 9 * 256 + 3 * 32 * 9 * 256;
    pack_weights<<<(total + 255) / 256, 256>>>(w0, w1, wcx0, wch0, wcx1, wch1);

    const int smem_bytes = SMEM_FLOATS * 4;
    cudaFuncSetAttribute(polyrnn_main, cudaFuncAttributeMaxDynamicSharedMemorySize, smem_bytes);
    polyrnn_main<<<n, 256, smem_bytes>>>(x, fv, b0, b1, bcx0, bch0, bcx1, bch1, fcw, fcb, out);
}